// round 15
// baseline (speedup 1.0000x reference)
#include <cuda_runtime.h>
#include <cuda_fp16.h>
#include <math.h>
#include <mma.h>

using namespace nvcuda;

#define N_NODES   100000
#define MAX_E     3300000
#define D         128
#define D_FF      256
#define N_CLASSES 26
#define N_GRAPHS  512
#define SCAN_BLK  1024
#define GATHER_CHUNK 16

// ---------------- scratch (static __device__ — allocation-guard safe) -------
__device__ __half g_h   [(size_t)N_NODES * D];   // fp16 messages (GEMM out)
__device__ __half g_acth[(size_t)N_NODES * D];   // fp16 activations (GEMM in)
__device__ __half g_Wh  [3][D * D];              // preconverted fp16 weights
__device__ int    g_edeg[N_NODES];
__device__ float  g_dinv[N_NODES];
__device__ int    g_off [N_NODES + 1];
__device__ int    g_fill[N_NODES];
__device__ int    g_bsum[256];
__device__ int2   g_csr [MAX_E];                 // (src, weight-bits)
__device__ int    g_batch[N_NODES];
__device__ float  g_psum[N_GRAPHS * D];
__device__ int    g_cnt [N_GRAPHS];
__device__ int    g_is64;
__device__ int    g_work[4];                     // dynamic gather counters

// ---------------- helpers ---------------------------------------------------
__device__ __forceinline__ long long load_index(const void* p, long long pos, int is64) {
    if (is64) return ((const long long*)p)[pos];
    return (long long)((const int*)p)[pos];
}

__device__ __forceinline__ void red_add_v4(float* addr, float4 v) {
    asm volatile("red.global.add.v4.f32 [%0], {%1, %2, %3, %4};"
                 :: "l"(addr), "f"(v.x), "f"(v.y), "f"(v.z), "f"(v.w)
                 : "memory");
}

__device__ __forceinline__ void fma8_h(float4& a, float4& b, uint4 hv, float w) {
    float2 f0 = __half22float2(*(__half2*)&hv.x);
    float2 f1 = __half22float2(*(__half2*)&hv.y);
    float2 f2 = __half22float2(*(__half2*)&hv.z);
    float2 f3 = __half22float2(*(__half2*)&hv.w);
    a.x = fmaf(w, f0.x, a.x); a.y = fmaf(w, f0.y, a.y);
    a.z = fmaf(w, f1.x, a.z); a.w = fmaf(w, f1.y, a.w);
    b.x = fmaf(w, f2.x, b.x); b.y = fmaf(w, f2.y, b.y);
    b.z = fmaf(w, f3.x, b.z); b.w = fmaf(w, f3.y, b.w);
}

__device__ __forceinline__ uint2 pack4_h(float4 v) {
    __half2 a = __floats2half2_rn(v.x, v.y);
    __half2 b = __floats2half2_rn(v.z, v.w);
    uint2 r;
    r.x = *(unsigned*)&a;
    r.y = *(unsigned*)&b;
    return r;
}

// ---------------- setup kernels ---------------------------------------------
__global__ void init_kernel(const int* ei, int n) {
    int i = blockIdx.x * blockDim.x + threadIdx.x;
    if (i == 0) {
        int all0 = 1;
        #pragma unroll
        for (int k = 1; k < 64; k += 2) all0 &= (ei[k] == 0);
        g_is64 = all0;
    }
    if (i < 4) g_work[i] = 0;
    if (i < n) g_edeg[i] = 0;
    if (i < N_GRAPHS * D) g_psum[i] = 0.f;
    if (i < N_GRAPHS) g_cnt[i] = 0;
}

__global__ void convert_x_kernel(const float* __restrict__ x, int n) {
    long long i = blockIdx.x * (long long)blockDim.x + threadIdx.x;
    long long total = (long long)n * 16;
    if (i < total) {
        float4 a = ((const float4*)x)[i * 2];
        float4 b = ((const float4*)x)[i * 2 + 1];
        uint2 p0 = pack4_h(a);
        uint2 p1 = pack4_h(b);
        ((uint4*)g_acth)[i] = make_uint4(p0.x, p0.y, p1.x, p1.y);
    }
}

__global__ void convW_kernel(const float* __restrict__ W1,
                             const float* __restrict__ W2,
                             const float* __restrict__ W3) {
    int i = blockIdx.x * blockDim.x + threadIdx.x;
    if (i < 3 * 4096) {
        int sel = i >> 12, j = i & 4095;
        const float* W = sel == 0 ? W1 : (sel == 1 ? W2 : W3);
        float4 w = ((const float4*)W)[j];
        ((uint2*)g_Wh[sel])[j] = pack4_h(w);
    }
}

__global__ void degree_kernel(const void* ei, int E) {
    int is64 = g_is64;
    long long stride = (long long)gridDim.x * blockDim.x;
    long long tid = blockIdx.x * (long long)blockDim.x + threadIdx.x;
    if (is64) {
        const long long* dst = (const long long*)ei + E;
        int half = E >> 1;
        const longlong2* p = (const longlong2*)dst;
        for (long long i = tid; i < half; i += stride) {
            longlong2 v = p[i];
            atomicAdd(&g_edeg[(int)v.x], 1);
            atomicAdd(&g_edeg[(int)v.y], 1);
        }
        if (tid == 0 && (E & 1)) atomicAdd(&g_edeg[(int)dst[E - 1]], 1);
    } else {
        const int* dst = (const int*)ei + E;
        int q = E >> 2;
        const int4* p = (const int4*)dst;
        for (long long i = tid; i < q; i += stride) {
            int4 v = p[i];
            atomicAdd(&g_edeg[v.x], 1); atomicAdd(&g_edeg[v.y], 1);
            atomicAdd(&g_edeg[v.z], 1); atomicAdd(&g_edeg[v.w], 1);
        }
        if (tid < (E & 3)) atomicAdd(&g_edeg[dst[(q << 2) + tid]], 1);
    }
}

__global__ void scanA_kernel(int n) {
    __shared__ int ssum[256];
    int b = blockIdx.x, t = threadIdx.x;
    int base = b * SCAN_BLK + t * 4;
    int v[4];
    #pragma unroll
    for (int j = 0; j < 4; j++) {
        int idx = base + j;
        v[j] = (idx < n) ? g_edeg[idx] : 0;
        if (idx < n) g_dinv[idx] = rsqrtf((float)(v[j] + 1));
    }
    int tot = v[0] + v[1] + v[2] + v[3];
    ssum[t] = tot;
    __syncthreads();
    #pragma unroll
    for (int ofs = 1; ofs < 256; ofs <<= 1) {
        int val = (t >= ofs) ? ssum[t - ofs] : 0;
        __syncthreads();
        ssum[t] += val;
        __syncthreads();
    }
    int excl = ssum[t] - tot;
    int run = excl;
    #pragma unroll
    for (int j = 0; j < 4; j++) {
        int idx = base + j;
        if (idx < n) g_off[idx] = run;
        run += v[j];
    }
    if (t == 255) g_bsum[b] = ssum[255];
}

__global__ void scanB_kernel(int nb, int n) {
    if (threadIdx.x == 0 && blockIdx.x == 0) {
        int run = 0;
        for (int b = 0; b < nb; b++) {
            int t = g_bsum[b];
            g_bsum[b] = run;
            run += t;
        }
        g_off[n] = run;
    }
}

__global__ void scanC_kernel(const void* batch, int n) {
    int i = blockIdx.x * blockDim.x + threadIdx.x;
    if (i < n) {
        int o = g_off[i] + g_bsum[i / SCAN_BLK];
        g_off[i] = o;
        g_fill[i] = o;
        int g = (int)load_index(batch, i, g_is64);
        g_batch[i] = g;
        atomicAdd(&g_cnt[g], 1);
    }
}

__device__ __forceinline__ void fill_one(int s, int d) {
    int pos = atomicAdd(&g_fill[d], 1);
    float w = g_dinv[s] * g_dinv[d];
    g_csr[pos] = make_int2(s, __float_as_int(w));
}

__global__ void fill_kernel(const void* ei, int E) {
    int is64 = g_is64;
    long long stride = (long long)gridDim.x * blockDim.x;
    long long tid = blockIdx.x * (long long)blockDim.x + threadIdx.x;
    if (is64) {
        const long long* sp = (const long long*)ei;
        const long long* dp = sp + E;
        int half = E >> 1;
        for (long long i = tid; i < half; i += stride) {
            longlong2 s2 = ((const longlong2*)sp)[i];
            longlong2 d2 = ((const longlong2*)dp)[i];
            fill_one((int)s2.x, (int)d2.x);
            fill_one((int)s2.y, (int)d2.y);
        }
        if (tid == 0 && (E & 1)) fill_one((int)sp[E - 1], (int)dp[E - 1]);
    } else {
        const int* sp = (const int*)ei;
        const int* dp = sp + E;
        int q = E >> 2;
        for (long long i = tid; i < q; i += stride) {
            int4 s4 = ((const int4*)sp)[i];
            int4 d4 = ((const int4*)dp)[i];
            fill_one(s4.x, d4.x); fill_one(s4.y, d4.y);
            fill_one(s4.z, d4.z); fill_one(s4.w, d4.w);
        }
        if (tid < (E & 3)) {
            int j = (q << 2) + (int)tid;
            fill_one(sp[j], dp[j]);
        }
    }
}

// ---------------- fp16 tensor-core GEMM: 64x128 tile, direct fp16 store -----
#define AH_LD 136
__global__ void gcn_gemm_tc16_kernel(int layer, int n) {
    extern __shared__ char smc[];
    __half* Ws = (__half*)smc;                   // 128 x AH_LD
    __half* As = Ws + 128 * AH_LD;               // 64 x AH_LD

    const __half* Wh = g_Wh[layer];
    int row0 = blockIdx.x * 64;
    int t = threadIdx.x;
    int rows = n - row0; if (rows > 64) rows = 64;

    for (int i = t; i < 128 * 16; i += 256) {
        int r = i >> 4, c8 = (i & 15) << 3;
        *(uint4*)(Ws + r * AH_LD + c8) = *(const uint4*)(Wh + r * D + c8);
    }
    for (int i = t; i < 64 * 16; i += 256) {
        int r = i >> 4, c8 = (i & 15) << 3;
        uint4 v;
        if (r < rows)
            v = *(const uint4*)(g_acth + (size_t)(row0 + r) * D + c8);
        else
            v = make_uint4(0, 0, 0, 0);
        *(uint4*)(As + r * AH_LD + c8) = v;
    }
    __syncthreads();

    int warp = t >> 5;
    int wrow = warp & 3;
    int wcol = warp >> 2;

    wmma::fragment<wmma::accumulator, 16, 16, 16, float> acc[4];
    #pragma unroll
    for (int j = 0; j < 4; j++) wmma::fill_fragment(acc[j], 0.f);

    const __half* arow = As + wrow * 16 * AH_LD;
    #pragma unroll
    for (int k0 = 0; k0 < 128; k0 += 16) {
        wmma::fragment<wmma::matrix_a, 16, 16, 16, __half, wmma::row_major> af;
        wmma::load_matrix_sync(af, arow + k0, AH_LD);
        #pragma unroll
        for (int nc = 0; nc < 4; nc++) {
            int ncol = wcol * 64 + nc * 16;
            wmma::fragment<wmma::matrix_b, 16, 16, 16, __half, wmma::row_major> bf;
            wmma::load_matrix_sync(bf, Ws + k0 * AH_LD + ncol, AH_LD);
            wmma::mma_sync(acc[nc], af, bf, acc[nc]);
        }
    }

    int rbase = row0 + wrow * 16;
    if (rbase < n) {   // n % 16 == 0 -> fragment fully valid
        #pragma unroll
        for (int nc = 0; nc < 4; nc++) {
            wmma::fragment<wmma::accumulator, 16, 16, 16, __half> hacc;
            #pragma unroll
            for (int e = 0; e < 8; e++) hacc.x[e] = __float2half(acc[nc].x[e]);
            int ncol = wcol * 64 + nc * 16;
            wmma::store_matrix_sync(g_h + (size_t)rbase * D + ncol, hacc, D,
                                    wmma::mem_row_major);
        }
    }
}

// ---------------- gather: dynamic work-stealing, half-warp per node ----------
// Blocks pop 16-node chunks from g_work[which]; late CTAs do fewer chunks,
// removing multi-CTA spread + last-wave tail.
__global__ void gather_kernel(const float* __restrict__ bias, int n,
                              int do_pool, int which) {
    __shared__ int sbase;
    int t = threadIdx.x;
    int lane = t & 15;
    int sub = t >> 4;             // 0..15: half-warp index within block

    const uint4* hp = (const uint4*)g_h;

    for (;;) {
        if (t == 0) sbase = atomicAdd(&g_work[which], GATHER_CHUNK);
        __syncthreads();
        int base = sbase;
        __syncthreads();
        if (base >= n) break;

        int nd = base + sub;
        if (nd < n) {
            float dv = g_dinv[nd];
            float d2 = dv * dv;

            float4 accA = make_float4(0.f, 0.f, 0.f, 0.f);
            float4 accB = make_float4(0.f, 0.f, 0.f, 0.f);
            fma8_h(accA, accB, hp[(size_t)nd * 16 + lane], d2);

            int beg = g_off[nd];
            int end = g_off[nd + 1];
            int e = beg;
            for (; e + 3 < end; e += 4) {
                int2 r0 = __ldg(&g_csr[e]);
                int2 r1 = __ldg(&g_csr[e + 1]);
                int2 r2 = __ldg(&g_csr[e + 2]);
                int2 r3 = __ldg(&g_csr[e + 3]);
                uint4 v0 = hp[(size_t)r0.x * 16 + lane];
                uint4 v1 = hp[(size_t)r1.x * 16 + lane];
                uint4 v2 = hp[(size_t)r2.x * 16 + lane];
                uint4 v3 = hp[(size_t)r3.x * 16 + lane];
                fma8_h(accA, accB, v0, __int_as_float(r0.y));
                fma8_h(accA, accB, v1, __int_as_float(r1.y));
                fma8_h(accA, accB, v2, __int_as_float(r2.y));
                fma8_h(accA, accB, v3, __int_as_float(r3.y));
            }
            for (; e < end; e++) {
                int2 r = __ldg(&g_csr[e]);
                fma8_h(accA, accB, hp[(size_t)r.x * 16 + lane], __int_as_float(r.y));
            }

            float4 b0 = ((const float4*)bias)[lane * 2];
            float4 b1 = ((const float4*)bias)[lane * 2 + 1];
            accA.x = fmaxf(accA.x + b0.x, 0.f);
            accA.y = fmaxf(accA.y + b0.y, 0.f);
            accA.z = fmaxf(accA.z + b0.z, 0.f);
            accA.w = fmaxf(accA.w + b0.w, 0.f);
            accB.x = fmaxf(accB.x + b1.x, 0.f);
            accB.y = fmaxf(accB.y + b1.y, 0.f);
            accB.z = fmaxf(accB.z + b1.z, 0.f);
            accB.w = fmaxf(accB.w + b1.w, 0.f);

            if (do_pool) {
                int g = g_batch[nd];
                float* pbase = g_psum + (size_t)g * D + lane * 8;
                red_add_v4(pbase, accA);
                red_add_v4(pbase + 4, accB);
            } else {
                uint2 pA = pack4_h(accA);
                uint2 pB = pack4_h(accB);
                ((uint4*)g_acth)[(size_t)nd * 16 + lane] =
                    make_uint4(pA.x, pA.y, pB.x, pB.y);
            }
        }
    }
}

// ---------------- fused MLP head ---------------------------------------------
__global__ void fc_kernel(const float* __restrict__ Wfc, const float* __restrict__ bfc,
                          const float* __restrict__ Wfc2, const float* __restrict__ bfc2,
                          float* __restrict__ out) {
    __shared__ float p[D];
    __shared__ float h1[D_FF];
    int g = blockIdx.x;
    int t = threadIdx.x;

    int c = g_cnt[g]; if (c < 1) c = 1;
    float inv = 1.f / (float)c;
    if (t < D) p[t] = g_psum[g * D + t] * inv;
    __syncthreads();

    float s = bfc[t];
    #pragma unroll 4
    for (int k = 0; k < D; k++) s = fmaf(p[k], Wfc[k * D_FF + t], s);
    h1[t] = fmaxf(s, 0.f);
    __syncthreads();

    if (t < N_CLASSES) {
        float s2 = bfc2[t];
        #pragma unroll 4
        for (int k = 0; k < D_FF; k++) s2 = fmaf(h1[k], Wfc2[k * N_CLASSES + t], s2);
        out[g * N_CLASSES + t] = s2;
    }
}

// ---------------- launch -----------------------------------------------------
extern "C" void kernel_launch(void* const* d_in, const int* in_sizes, int n_in,
                              void* d_out, int out_size) {
    const float* x    = (const float*)d_in[0];
    const void*  ei   = d_in[1];
    const void*  batch= d_in[2];
    const float* W1   = (const float*)d_in[3];
    const float* b1   = (const float*)d_in[4];
    const float* W2   = (const float*)d_in[5];
    const float* b2   = (const float*)d_in[6];
    const float* W3   = (const float*)d_in[7];
    const float* b3   = (const float*)d_in[8];
    const float* Wfc  = (const float*)d_in[9];
    const float* bfc  = (const float*)d_in[10];
    const float* Wfc2 = (const float*)d_in[11];
    const float* bfc2 = (const float*)d_in[12];
    float* out = (float*)d_out;

    int n = in_sizes[0] / D;
    int E = in_sizes[1] / 2;

    const int GEMM_SMEM = (128 + 64) * AH_LD * 2;   // 52224 B

    static bool once_done = false;
    static cudaStream_t s1;
    static cudaEvent_t ev_fork, ev_join;
    if (!once_done) {
        cudaFuncSetAttribute(gcn_gemm_tc16_kernel,
                             cudaFuncAttributeMaxDynamicSharedMemorySize, GEMM_SMEM);
        cudaStreamCreateWithFlags(&s1, cudaStreamNonBlocking);
        cudaEventCreateWithFlags(&ev_fork, cudaEventDisableTiming);
        cudaEventCreateWithFlags(&ev_join, cudaEventDisableTiming);
        once_done = true;
    }

    int gemm_blocks = (n + 63) / 64;
    int gather_blocks = 2048;   // work-stealing: near-resident grid
    int nb = (n + SCAN_BLK - 1) / SCAN_BLK;

    // ---- fork: feature path on s1, graph-structure path on capture stream ----
    init_kernel<<<(n + 255) / 256, 256>>>((const int*)ei, n);
    cudaEventRecord(ev_fork, 0);
    cudaStreamWaitEvent(s1, ev_fork, 0);

    // s1: x->fp16, W->fp16, layer-1 GEMM
    convert_x_kernel<<<(n * 16 + 255) / 256, 256, 0, s1>>>(x, n);
    convW_kernel<<<(3 * 4096 + 255) / 256, 256, 0, s1>>>(W1, W2, W3);
    gcn_gemm_tc16_kernel<<<gemm_blocks, 256, GEMM_SMEM, s1>>>(0, n);
    cudaEventRecord(ev_join, s1);

    // capture stream: degree -> scan -> CSR fill
    degree_kernel<<<2048, 256>>>(ei, E);
    scanA_kernel<<<nb, 256>>>(n);
    scanB_kernel<<<1, 32>>>(nb, n);
    scanC_kernel<<<(n + 255) / 256, 256>>>(batch, n);
    fill_kernel<<<2048, 256>>>(ei, E);
    cudaStreamWaitEvent(0, ev_join, 0);

    // ---- layers (sequential) ----
    gather_kernel<<<gather_blocks, 256>>>(b1, n, 0, 0);

    gcn_gemm_tc16_kernel<<<gemm_blocks, 256, GEMM_SMEM>>>(1, n);
    gather_kernel<<<gather_blocks, 256>>>(b2, n, 0, 1);

    gcn_gemm_tc16_kernel<<<gemm_blocks, 256, GEMM_SMEM>>>(2, n);
    gather_kernel<<<gather_blocks, 256>>>(b3, n, 1, 2);

    fc_kernel<<<N_GRAPHS, D_FF>>>(Wfc, bfc, Wfc2, bfc2, out);
}

// round 16
// speedup vs baseline: 1.0414x; 1.0414x over previous
#include <cuda_runtime.h>
#include <cuda_fp16.h>
#include <math.h>
#include <mma.h>

using namespace nvcuda;

#define N_NODES   100000
#define MAX_E     3300000
#define D         128
#define D_FF      256
#define N_CLASSES 26
#define N_GRAPHS  512
#define SCAN_BLK  1024

// ---------------- scratch (static __device__ — allocation-guard safe) -------
__device__ __half g_h   [(size_t)N_NODES * D];   // fp16 messages (GEMM out)
__device__ __half g_acth[(size_t)N_NODES * D];   // fp16 activations (GEMM in)
__device__ __half g_Wh  [3][D * D];              // preconverted fp16 weights
__device__ int    g_edeg[N_NODES];
__device__ float  g_dinv[N_NODES];
__device__ int    g_off [N_NODES + 1];
__device__ int    g_fill[N_NODES];
__device__ int    g_bsum[256];
__device__ int2   g_csr [MAX_E];                 // (src, weight-bits)
__device__ int    g_batch[N_NODES];
__device__ float  g_psum[N_GRAPHS * D];
__device__ int    g_cnt [N_GRAPHS];
__device__ int    g_is64;

// ---------------- helpers ---------------------------------------------------
__device__ __forceinline__ long long load_index(const void* p, long long pos, int is64) {
    if (is64) return ((const long long*)p)[pos];
    return (long long)((const int*)p)[pos];
}

__device__ __forceinline__ void red_add_v4(float* addr, float4 v) {
    asm volatile("red.global.add.v4.f32 [%0], {%1, %2, %3, %4};"
                 :: "l"(addr), "f"(v.x), "f"(v.y), "f"(v.z), "f"(v.w)
                 : "memory");
}

__device__ __forceinline__ void fma8_h(float4& a, float4& b, uint4 hv, float w) {
    float2 f0 = __half22float2(*(__half2*)&hv.x);
    float2 f1 = __half22float2(*(__half2*)&hv.y);
    float2 f2 = __half22float2(*(__half2*)&hv.z);
    float2 f3 = __half22float2(*(__half2*)&hv.w);
    a.x = fmaf(w, f0.x, a.x); a.y = fmaf(w, f0.y, a.y);
    a.z = fmaf(w, f1.x, a.z); a.w = fmaf(w, f1.y, a.w);
    b.x = fmaf(w, f2.x, b.x); b.y = fmaf(w, f2.y, b.y);
    b.z = fmaf(w, f3.x, b.z); b.w = fmaf(w, f3.y, b.w);
}

__device__ __forceinline__ uint2 pack4_h(float4 v) {
    __half2 a = __floats2half2_rn(v.x, v.y);
    __half2 b = __floats2half2_rn(v.z, v.w);
    uint2 r;
    r.x = *(unsigned*)&a;
    r.y = *(unsigned*)&b;
    return r;
}

// ---------------- setup kernels ---------------------------------------------
__global__ void init_kernel(const int* ei, int n) {
    int i = blockIdx.x * blockDim.x + threadIdx.x;
    if (i == 0) {
        int all0 = 1;
        #pragma unroll
        for (int k = 1; k < 64; k += 2) all0 &= (ei[k] == 0);
        g_is64 = all0;
    }
    if (i < n) g_edeg[i] = 0;
    if (i < N_GRAPHS * D) g_psum[i] = 0.f;
    if (i < N_GRAPHS) g_cnt[i] = 0;
}

__global__ void convW_kernel(const float* __restrict__ W1,
                             const float* __restrict__ W2,
                             const float* __restrict__ W3) {
    int i = blockIdx.x * blockDim.x + threadIdx.x;
    if (i < 3 * 4096) {
        int sel = i >> 12, j = i & 4095;
        const float* W = sel == 0 ? W1 : (sel == 1 ? W2 : W3);
        float4 w = ((const float4*)W)[j];
        ((uint2*)g_Wh[sel])[j] = pack4_h(w);
    }
}

__global__ void degree_kernel(const void* ei, int E) {
    int is64 = g_is64;
    long long stride = (long long)gridDim.x * blockDim.x;
    long long tid = blockIdx.x * (long long)blockDim.x + threadIdx.x;
    if (is64) {
        const long long* dst = (const long long*)ei + E;
        int half = E >> 1;
        const longlong2* p = (const longlong2*)dst;
        for (long long i = tid; i < half; i += stride) {
            longlong2 v = p[i];
            atomicAdd(&g_edeg[(int)v.x], 1);
            atomicAdd(&g_edeg[(int)v.y], 1);
        }
        if (tid == 0 && (E & 1)) atomicAdd(&g_edeg[(int)dst[E - 1]], 1);
    } else {
        const int* dst = (const int*)ei + E;
        int q = E >> 2;
        const int4* p = (const int4*)dst;
        for (long long i = tid; i < q; i += stride) {
            int4 v = p[i];
            atomicAdd(&g_edeg[v.x], 1); atomicAdd(&g_edeg[v.y], 1);
            atomicAdd(&g_edeg[v.z], 1); atomicAdd(&g_edeg[v.w], 1);
        }
        if (tid < (E & 3)) atomicAdd(&g_edeg[dst[(q << 2) + tid]], 1);
    }
}

__global__ void scanA_kernel(int n) {
    __shared__ int ssum[256];
    int b = blockIdx.x, t = threadIdx.x;
    int base = b * SCAN_BLK + t * 4;
    int v[4];
    #pragma unroll
    for (int j = 0; j < 4; j++) {
        int idx = base + j;
        v[j] = (idx < n) ? g_edeg[idx] : 0;
        if (idx < n) g_dinv[idx] = rsqrtf((float)(v[j] + 1));
    }
    int tot = v[0] + v[1] + v[2] + v[3];
    ssum[t] = tot;
    __syncthreads();
    #pragma unroll
    for (int ofs = 1; ofs < 256; ofs <<= 1) {
        int val = (t >= ofs) ? ssum[t - ofs] : 0;
        __syncthreads();
        ssum[t] += val;
        __syncthreads();
    }
    int excl = ssum[t] - tot;
    int run = excl;
    #pragma unroll
    for (int j = 0; j < 4; j++) {
        int idx = base + j;
        if (idx < n) g_off[idx] = run;
        run += v[j];
    }
    if (t == 255) g_bsum[b] = ssum[255];
}

__global__ void scanB_kernel(int nb, int n) {
    if (threadIdx.x == 0 && blockIdx.x == 0) {
        int run = 0;
        for (int b = 0; b < nb; b++) {
            int t = g_bsum[b];
            g_bsum[b] = run;
            run += t;
        }
        g_off[n] = run;
    }
}

__global__ void scanC_kernel(const void* batch, int n) {
    int i = blockIdx.x * blockDim.x + threadIdx.x;
    if (i < n) {
        int o = g_off[i] + g_bsum[i / SCAN_BLK];
        g_off[i] = o;
        g_fill[i] = o;
        int g = (int)load_index(batch, i, g_is64);
        g_batch[i] = g;
        atomicAdd(&g_cnt[g], 1);
    }
}

__device__ __forceinline__ void fill_one(int s, int d) {
    int pos = atomicAdd(&g_fill[d], 1);
    float w = g_dinv[s] * g_dinv[d];
    g_csr[pos] = make_int2(s, __float_as_int(w));
}

__global__ void fill_kernel(const void* ei, int E) {
    int is64 = g_is64;
    long long stride = (long long)gridDim.x * blockDim.x;
    long long tid = blockIdx.x * (long long)blockDim.x + threadIdx.x;
    if (is64) {
        const long long* sp = (const long long*)ei;
        const long long* dp = sp + E;
        int half = E >> 1;
        for (long long i = tid; i < half; i += stride) {
            longlong2 s2 = ((const longlong2*)sp)[i];
            longlong2 d2 = ((const longlong2*)dp)[i];
            fill_one((int)s2.x, (int)d2.x);
            fill_one((int)s2.y, (int)d2.y);
        }
        if (tid == 0 && (E & 1)) fill_one((int)sp[E - 1], (int)dp[E - 1]);
    } else {
        const int* sp = (const int*)ei;
        const int* dp = sp + E;
        int q = E >> 2;
        for (long long i = tid; i < q; i += stride) {
            int4 s4 = ((const int4*)sp)[i];
            int4 d4 = ((const int4*)dp)[i];
            fill_one(s4.x, d4.x); fill_one(s4.y, d4.y);
            fill_one(s4.z, d4.z); fill_one(s4.w, d4.w);
        }
        if (tid < (E & 3)) {
            int j = (q << 2) + (int)tid;
            fill_one(sp[j], dp[j]);
        }
    }
}

// ---------------- fp16 tensor-core GEMM: 64x128 tile, direct fp16 store -----
// use_x: layer 0 reads fp32 x directly, converting during smem staging
// (fuses the convert_x pass into the GEMM). Layers 1/2 read g_acth fp16.
#define AH_LD 136
__global__ void gcn_gemm_tc16_kernel(int layer, int n,
                                     const float* __restrict__ Xf, int use_x) {
    extern __shared__ char smc[];
    __half* Ws = (__half*)smc;                   // 128 x AH_LD
    __half* As = Ws + 128 * AH_LD;               // 64 x AH_LD

    const __half* Wh = g_Wh[layer];
    int row0 = blockIdx.x * 64;
    int t = threadIdx.x;
    int rows = n - row0; if (rows > 64) rows = 64;

    for (int i = t; i < 128 * 16; i += 256) {
        int r = i >> 4, c8 = (i & 15) << 3;
        *(uint4*)(Ws + r * AH_LD + c8) = *(const uint4*)(Wh + r * D + c8);
    }
    if (use_x) {
        // stage A from fp32 x with inline conversion
        for (int i = t; i < 64 * 16; i += 256) {
            int r = i >> 4, c8 = (i & 15) << 3;
            uint4 v;
            if (r < rows) {
                const float* p = Xf + (size_t)(row0 + r) * D + c8;
                float4 a = *(const float4*)p;
                float4 b = *(const float4*)(p + 4);
                uint2 p0 = pack4_h(a);
                uint2 p1 = pack4_h(b);
                v = make_uint4(p0.x, p0.y, p1.x, p1.y);
            } else {
                v = make_uint4(0, 0, 0, 0);
            }
            *(uint4*)(As + r * AH_LD + c8) = v;
        }
    } else {
        for (int i = t; i < 64 * 16; i += 256) {
            int r = i >> 4, c8 = (i & 15) << 3;
            uint4 v;
            if (r < rows)
                v = *(const uint4*)(g_acth + (size_t)(row0 + r) * D + c8);
            else
                v = make_uint4(0, 0, 0, 0);
            *(uint4*)(As + r * AH_LD + c8) = v;
        }
    }
    __syncthreads();

    int warp = t >> 5;
    int wrow = warp & 3;
    int wcol = warp >> 2;

    wmma::fragment<wmma::accumulator, 16, 16, 16, float> acc[4];
    #pragma unroll
    for (int j = 0; j < 4; j++) wmma::fill_fragment(acc[j], 0.f);

    const __half* arow = As + wrow * 16 * AH_LD;
    #pragma unroll
    for (int k0 = 0; k0 < 128; k0 += 16) {
        wmma::fragment<wmma::matrix_a, 16, 16, 16, __half, wmma::row_major> af;
        wmma::load_matrix_sync(af, arow + k0, AH_LD);
        #pragma unroll
        for (int nc = 0; nc < 4; nc++) {
            int ncol = wcol * 64 + nc * 16;
            wmma::fragment<wmma::matrix_b, 16, 16, 16, __half, wmma::row_major> bf;
            wmma::load_matrix_sync(bf, Ws + k0 * AH_LD + ncol, AH_LD);
            wmma::mma_sync(acc[nc], af, bf, acc[nc]);
        }
    }

    // direct epilogue: f32 frag -> f16 frag -> global store, stride D.
    int rbase = row0 + wrow * 16;
    if (rbase < n) {   // n % 16 == 0 -> fragment fully valid
        #pragma unroll
        for (int nc = 0; nc < 4; nc++) {
            wmma::fragment<wmma::accumulator, 16, 16, 16, __half> hacc;
            #pragma unroll
            for (int e = 0; e < 8; e++) hacc.x[e] = __float2half(acc[nc].x[e]);
            int ncol = wcol * 64 + nc * 16;
            wmma::store_matrix_sync(g_h + (size_t)rbase * D + ncol, hacc, D,
                                    wmma::mem_row_major);
        }
    }
}

// ---------------- gather: HALF-WARP per node, 16B lanes, fused epilogue -----
__global__ void gather_kernel(const float* __restrict__ bias, int n, int do_pool) {
    int hw = (blockIdx.x * blockDim.x + threadIdx.x) >> 4;
    if (hw >= n) return;
    int lane = threadIdx.x & 15;
    int nd = hw;

    const uint4* hp = (const uint4*)g_h;
    float dv = g_dinv[nd];
    float d2 = dv * dv;

    float4 accA = make_float4(0.f, 0.f, 0.f, 0.f);
    float4 accB = make_float4(0.f, 0.f, 0.f, 0.f);
    fma8_h(accA, accB, hp[(size_t)nd * 16 + lane], d2);

    int beg = g_off[nd];
    int end = g_off[nd + 1];
    int e = beg;
    for (; e + 3 < end; e += 4) {
        int2 r0 = __ldg(&g_csr[e]);
        int2 r1 = __ldg(&g_csr[e + 1]);
        int2 r2 = __ldg(&g_csr[e + 2]);
        int2 r3 = __ldg(&g_csr[e + 3]);
        uint4 v0 = hp[(size_t)r0.x * 16 + lane];
        uint4 v1 = hp[(size_t)r1.x * 16 + lane];
        uint4 v2 = hp[(size_t)r2.x * 16 + lane];
        uint4 v3 = hp[(size_t)r3.x * 16 + lane];
        fma8_h(accA, accB, v0, __int_as_float(r0.y));
        fma8_h(accA, accB, v1, __int_as_float(r1.y));
        fma8_h(accA, accB, v2, __int_as_float(r2.y));
        fma8_h(accA, accB, v3, __int_as_float(r3.y));
    }
    for (; e < end; e++) {
        int2 r = __ldg(&g_csr[e]);
        fma8_h(accA, accB, hp[(size_t)r.x * 16 + lane], __int_as_float(r.y));
    }

    float4 b0 = ((const float4*)bias)[lane * 2];
    float4 b1 = ((const float4*)bias)[lane * 2 + 1];
    accA.x = fmaxf(accA.x + b0.x, 0.f);
    accA.y = fmaxf(accA.y + b0.y, 0.f);
    accA.z = fmaxf(accA.z + b0.z, 0.f);
    accA.w = fmaxf(accA.w + b0.w, 0.f);
    accB.x = fmaxf(accB.x + b1.x, 0.f);
    accB.y = fmaxf(accB.y + b1.y, 0.f);
    accB.z = fmaxf(accB.z + b1.z, 0.f);
    accB.w = fmaxf(accB.w + b1.w, 0.f);

    if (do_pool) {
        int g = g_batch[nd];
        float* base = g_psum + (size_t)g * D + lane * 8;
        red_add_v4(base, accA);
        red_add_v4(base + 4, accB);
    } else {
        uint2 pA = pack4_h(accA);
        uint2 pB = pack4_h(accB);
        ((uint4*)g_acth)[(size_t)nd * 16 + lane] =
            make_uint4(pA.x, pA.y, pB.x, pB.y);
    }
}

// ---------------- fused MLP head ---------------------------------------------
__global__ void fc_kernel(const float* __restrict__ Wfc, const float* __restrict__ bfc,
                          const float* __restrict__ Wfc2, const float* __restrict__ bfc2,
                          float* __restrict__ out) {
    __shared__ float p[D];
    __shared__ float h1[D_FF];
    int g = blockIdx.x;
    int t = threadIdx.x;

    int c = g_cnt[g]; if (c < 1) c = 1;
    float inv = 1.f / (float)c;
    if (t < D) p[t] = g_psum[g * D + t] * inv;
    __syncthreads();

    float s = bfc[t];
    #pragma unroll 4
    for (int k = 0; k < D; k++) s = fmaf(p[k], Wfc[k * D_FF + t], s);
    h1[t] = fmaxf(s, 0.f);
    __syncthreads();

    if (t < N_CLASSES) {
        float s2 = bfc2[t];
        #pragma unroll 4
        for (int k = 0; k < D_FF; k++) s2 = fmaf(h1[k], Wfc2[k * N_CLASSES + t], s2);
        out[g * N_CLASSES + t] = s2;
    }
}

// ---------------- launch -----------------------------------------------------
extern "C" void kernel_launch(void* const* d_in, const int* in_sizes, int n_in,
                              void* d_out, int out_size) {
    const float* x    = (const float*)d_in[0];
    const void*  ei   = d_in[1];
    const void*  batch= d_in[2];
    const float* W1   = (const float*)d_in[3];
    const float* b1   = (const float*)d_in[4];
    const float* W2   = (const float*)d_in[5];
    const float* b2   = (const float*)d_in[6];
    const float* W3   = (const float*)d_in[7];
    const float* b3   = (const float*)d_in[8];
    const float* Wfc  = (const float*)d_in[9];
    const float* bfc  = (const float*)d_in[10];
    const float* Wfc2 = (const float*)d_in[11];
    const float* bfc2 = (const float*)d_in[12];
    float* out = (float*)d_out;

    int n = in_sizes[0] / D;
    int E = in_sizes[1] / 2;

    const int GEMM_SMEM = (128 + 64) * AH_LD * 2;   // 52224 B

    static bool once_done = false;
    static cudaStream_t s1;
    static cudaEvent_t ev_fork, ev_join;
    if (!once_done) {
        cudaFuncSetAttribute(gcn_gemm_tc16_kernel,
                             cudaFuncAttributeMaxDynamicSharedMemorySize, GEMM_SMEM);
        cudaStreamCreateWithFlags(&s1, cudaStreamNonBlocking);
        cudaEventCreateWithFlags(&ev_fork, cudaEventDisableTiming);
        cudaEventCreateWithFlags(&ev_join, cudaEventDisableTiming);
        once_done = true;
    }

    int gemm_blocks = (n + 63) / 64;
    int gather_blocks = (n * 16 + 255) / 256;
    int nb = (n + SCAN_BLK - 1) / SCAN_BLK;

    // ---- fork: feature path on s1, graph-structure path on capture stream ----
    init_kernel<<<(n + 255) / 256, 256>>>((const int*)ei, n);
    cudaEventRecord(ev_fork, 0);
    cudaStreamWaitEvent(s1, ev_fork, 0);

    // s1: W->fp16, layer-0 GEMM (reads fp32 x directly; convert fused)
    convW_kernel<<<(3 * 4096 + 255) / 256, 256, 0, s1>>>(W1, W2, W3);
    gcn_gemm_tc16_kernel<<<gemm_blocks, 256, GEMM_SMEM, s1>>>(0, n, x, 1);
    cudaEventRecord(ev_join, s1);

    // capture stream: degree -> scan -> CSR fill
    degree_kernel<<<2048, 256>>>(ei, E);
    scanA_kernel<<<nb, 256>>>(n);
    scanB_kernel<<<1, 32>>>(nb, n);
    scanC_kernel<<<(n + 255) / 256, 256>>>(batch, n);
    fill_kernel<<<2048, 256>>>(ei, E);
    cudaStreamWaitEvent(0, ev_join, 0);

    // ---- layers (sequential) ----
    gather_kernel<<<gather_blocks, 256>>>(b1, n, 0);

    gcn_gemm_tc16_kernel<<<gemm_blocks, 256, GEMM_SMEM>>>(1, n, x, 0);
    gather_kernel<<<gather_blocks, 256>>>(b2, n, 0);

    gcn_gemm_tc16_kernel<<<gemm_blocks, 256, GEMM_SMEM>>>(2, n, x, 0);
    gather_kernel<<<gather_blocks, 256>>>(b3, n, 1);

    fc_kernel<<<N_GRAPHS, D_FF>>>(Wfc, bfc, Wfc2, bfc2, out);
}